// round 4
// baseline (speedup 1.0000x reference)
#include <cuda_runtime.h>
#include <cuda_fp16.h>
#include <mma.h>
#include <cstdint>

using namespace nvcuda;

#define N_NODES 50000
#define N_EDGES 800000
#define F 128
#define GRM 128                 // M-tile (nodes per fused block)
#define LDA 136                 // padded leading dim (halves) for A/B tiles
#define LDC 36                  // padded leading dim (floats) for C scratch
#define CSR_T 1024
#define PER ((N_NODES + CSR_T - 1) / CSR_T)   // 49

// smem layout (bytes): A [128][136] fp16, B [128][136] fp16; C scratch reuses from 0
#define OFF_A 0
#define OFF_B (GRM * LDA * 2)                       // 34816
#define SMEM_FUSED (16 * 32 * LDC * 4)              // 73728 (>= A+B = 69632)

// ---- scratch (no allocation allowed -> __device__ globals) ----
__device__ int    g_deg_src[N_NODES];
__device__ int    g_deg_dst[N_NODES];
__device__ float  g_out_norm[N_NODES];
__device__ float  g_in_norm[N_NODES];
__device__ int    g_row_ptr[N_NODES + 1];
__device__ int    g_cursor[N_NODES];
__device__ int    g_col_idx[N_EDGES];
__device__ __half g_x0[N_NODES * F];   // feat * out_norm, fp16
__device__ __half g_x1[N_NODES * F];
__device__ __half g_x2[N_NODES * F];
__device__ float  g_vec[F];

// ---------------- setup ----------------
__global__ void k_init() {
    int i = blockIdx.x * blockDim.x + threadIdx.x;
    if (i < N_NODES) { g_deg_src[i] = 0; g_deg_dst[i] = 0; }
    if (i < F) g_vec[i] = 0.f;
}

__global__ void k_count(const int* __restrict__ src, const int* __restrict__ dst) {
    int e = blockIdx.x * blockDim.x + threadIdx.x;
    if (e < N_EDGES) {
        atomicAdd(&g_deg_src[src[e]], 1);
        atomicAdd(&g_deg_dst[dst[e]], 1);
    }
}

// single-block CSR builder: prefix sum of deg_dst + norms + cursor init
__global__ void k_csr() {
    __shared__ int s[CSR_T];
    int t = threadIdx.x;
    int base = t * PER;
    int sum = 0;
    for (int j = 0; j < PER; j++) {
        int i = base + j;
        if (i < N_NODES) sum += g_deg_dst[i];
    }
    s[t] = sum;
    __syncthreads();
    for (int off = 1; off < CSR_T; off <<= 1) {
        int x = 0;
        if (t >= off) x = s[t - off];
        __syncthreads();
        if (t >= off) s[t] += x;
        __syncthreads();
    }
    int run = s[t] - sum;   // exclusive prefix
    for (int j = 0; j < PER; j++) {
        int i = base + j;
        if (i < N_NODES) {
            int d = g_deg_dst[i];
            g_row_ptr[i] = run;
            g_cursor[i] = run;
            run += d;
            g_in_norm[i]  = rsqrtf((float)max(d, 1));
            g_out_norm[i] = rsqrtf((float)max(g_deg_src[i], 1));
        }
    }
    if (t == CSR_T - 1) g_row_ptr[N_NODES] = s[t];
}

__global__ void k_fill(const int* __restrict__ src, const int* __restrict__ dst) {
    int e = blockIdx.x * blockDim.x + threadIdx.x;
    if (e < N_EDGES) {
        int d = dst[e];
        int p = atomicAdd(&g_cursor[d], 1);
        g_col_idx[p] = src[e];
    }
}

// feat -> fp16, prescaled by out_norm
__global__ void k_prep(const float* __restrict__ feat) {
    int i = (blockIdx.x * blockDim.x + threadIdx.x) * 4;
    if (i >= N_NODES * F) return;
    float on = g_out_norm[i >> 7];
    float4 v = *(const float4*)&feat[i];
    __half2 h01 = __floats2half2_rn(v.x * on, v.y * on);
    __half2 h23 = __floats2half2_rn(v.z * on, v.w * on);
    uint2 pk;
    pk.x = *(uint32_t*)&h01;
    pk.y = *(uint32_t*)&h23;
    *(uint2*)&g_x0[i] = pk;
}

// ---------------- fused layer: gather -> smem fp16 -> wmma HMMA -> epilogue ----
__global__ void __launch_bounds__(512)
k_fused(const __half* __restrict__ x, const float* __restrict__ W,
        const float* __restrict__ b, __half* __restrict__ y) {
    extern __shared__ char smem[];
    __half* sA = (__half*)(smem + OFF_A);   // [128][LDA]
    __half* sB = (__half*)(smem + OFF_B);   // [128][LDA], B[k][n] = W[k][n]
    float*  sC = (float*)smem;              // per-warp [32][LDC], reused after sync

    int t = threadIdx.x, warp = t >> 5, lane = t & 31;
    int row0 = blockIdx.x * GRM;

    // load W (fp32 [k][n] row-major) -> sB fp16
    for (int i = t * 4; i < F * F; i += 2048) {
        int k = i >> 7, n = i & 127;
        float4 w = *(const float4*)&W[i];
        __half2 h01 = __floats2half2_rn(w.x, w.y);
        __half2 h23 = __floats2half2_rn(w.z, w.w);
        uint2 pk;
        pk.x = *(uint32_t*)&h01;
        pk.y = *(uint32_t*)&h23;
        *(uint2*)&sB[k * LDA + n] = pk;
    }

    // gather: warp per node, 8 rounds -> sA fp16
    const uint2* x2 = (const uint2*)x;
#pragma unroll 1
    for (int i = 0; i < 8; i++) {
        int lr = i * 16 + warp;
        int node = row0 + lr;
        float4 a0 = {0.f, 0.f, 0.f, 0.f};
        float4 a1 = {0.f, 0.f, 0.f, 0.f};
        if (node < N_NODES) {
            int beg = g_row_ptr[node], end = g_row_ptr[node + 1];
            int e = beg;
            for (; e + 1 < end; e += 2) {
                int s0 = g_col_idx[e], s1 = g_col_idx[e + 1];
                uint2 v0 = x2[s0 * 32 + lane];
                uint2 v1 = x2[s1 * 32 + lane];
                float2 p00 = __half22float2(*(__half2*)&v0.x);
                float2 p01 = __half22float2(*(__half2*)&v0.y);
                float2 p10 = __half22float2(*(__half2*)&v1.x);
                float2 p11 = __half22float2(*(__half2*)&v1.y);
                a0.x += p00.x; a0.y += p00.y; a0.z += p01.x; a0.w += p01.y;
                a1.x += p10.x; a1.y += p10.y; a1.z += p11.x; a1.w += p11.y;
            }
            if (e < end) {
                int s0 = g_col_idx[e];
                uint2 v0 = x2[s0 * 32 + lane];
                float2 p00 = __half22float2(*(__half2*)&v0.x);
                float2 p01 = __half22float2(*(__half2*)&v0.y);
                a0.x += p00.x; a0.y += p00.y; a0.z += p01.x; a0.w += p01.y;
            }
            float sc = g_in_norm[node];
            a0.x = (a0.x + a1.x) * sc;
            a0.y = (a0.y + a1.y) * sc;
            a0.z = (a0.z + a1.z) * sc;
            a0.w = (a0.w + a1.w) * sc;
        }
        __half2 h01 = __floats2half2_rn(a0.x, a0.y);
        __half2 h23 = __floats2half2_rn(a0.z, a0.w);
        uint2 pk;
        pk.x = *(uint32_t*)&h01;
        pk.y = *(uint32_t*)&h23;
        *(uint2*)&sA[lr * LDA + lane * 4] = pk;
    }
    __syncthreads();

    // GEMM: warp (wy, wx) computes rows wy*32..+31, cols wx*32..+31
    int wy = warp >> 2, wx = warp & 3;
    wmma::fragment<wmma::accumulator, 16, 16, 16, float> c[2][2];
#pragma unroll
    for (int i = 0; i < 2; i++)
#pragma unroll
        for (int j = 0; j < 2; j++) wmma::fill_fragment(c[i][j], 0.f);

#pragma unroll
    for (int k0 = 0; k0 < F; k0 += 16) {
        wmma::fragment<wmma::matrix_a, 16, 16, 16, __half, wmma::row_major> af[2];
        wmma::fragment<wmma::matrix_b, 16, 16, 16, __half, wmma::row_major> bf[2];
#pragma unroll
        for (int i = 0; i < 2; i++)
            wmma::load_matrix_sync(af[i], &sA[(wy * 32 + i * 16) * LDA + k0], LDA);
#pragma unroll
        for (int j = 0; j < 2; j++)
            wmma::load_matrix_sync(bf[j], &sB[k0 * LDA + wx * 32 + j * 16], LDA);
#pragma unroll
        for (int i = 0; i < 2; i++)
#pragma unroll
            for (int j = 0; j < 2; j++)
                wmma::mma_sync(c[i][j], af[i], bf[j], c[i][j]);
    }
    __syncthreads();   // all warps done reading sA/sB; reuse smem for C

    float* myC = sC + warp * (32 * LDC);
#pragma unroll
    for (int i = 0; i < 2; i++)
#pragma unroll
        for (int j = 0; j < 2; j++)
            wmma::store_matrix_sync(&myC[(i * 16) * LDC + j * 16], c[i][j], LDC,
                                    wmma::mem_row_major);
    __syncwarp();

    // epilogue: lane handles row (wy*32 + lane), cols wx*32..+31
    int grow = row0 + wy * 32 + lane;
    if (grow < N_NODES) {
        float on = g_out_norm[grow];
        const float* cr = &myC[lane * LDC];
        __half2 hv[16];
#pragma unroll
        for (int cc = 0; cc < 32; cc += 4) {
            float4 bv = *(const float4*)&b[wx * 32 + cc];
            float v0 = fmaxf(cr[cc]     + bv.x, 0.f) * on;
            float v1 = fmaxf(cr[cc + 1] + bv.y, 0.f) * on;
            float v2 = fmaxf(cr[cc + 2] + bv.z, 0.f) * on;
            float v3 = fmaxf(cr[cc + 3] + bv.w, 0.f) * on;
            hv[cc / 2]     = __floats2half2_rn(v0, v1);
            hv[cc / 2 + 1] = __floats2half2_rn(v2, v3);
        }
        uint4* dstp = (uint4*)(y + (size_t)grow * F + wx * 32);
        dstp[0] = *(uint4*)&hv[0];
        dstp[1] = *(uint4*)&hv[4];
        dstp[2] = *(uint4*)&hv[8];
        dstp[3] = *(uint4*)&hv[12];
    }
}

// layer-3 aggregation folded into a 128-vector (x already prescaled by out_norm):
// g_vec = (1/N) * sum_i in_norm[i] * sum_{e: dst=i} x[src]
__global__ void k_agg3(const __half* __restrict__ x) {
    __shared__ float sacc[F];
    int t = threadIdx.x;
    if (t < F) sacc[t] = 0.f;
    __syncthreads();
    int w = (blockIdx.x * blockDim.x + t) >> 5;
    int lane = t & 31;
    if (w < N_NODES) {
        int beg = g_row_ptr[w], end = g_row_ptr[w + 1];
        const uint2* x2 = (const uint2*)x;
        float4 a0 = {0.f, 0.f, 0.f, 0.f};
        float4 a1 = {0.f, 0.f, 0.f, 0.f};
        int e = beg;
        for (; e + 1 < end; e += 2) {
            int s0 = g_col_idx[e], s1 = g_col_idx[e + 1];
            uint2 v0 = x2[s0 * 32 + lane];
            uint2 v1 = x2[s1 * 32 + lane];
            float2 p00 = __half22float2(*(__half2*)&v0.x);
            float2 p01 = __half22float2(*(__half2*)&v0.y);
            float2 p10 = __half22float2(*(__half2*)&v1.x);
            float2 p11 = __half22float2(*(__half2*)&v1.y);
            a0.x += p00.x; a0.y += p00.y; a0.z += p01.x; a0.w += p01.y;
            a1.x += p10.x; a1.y += p10.y; a1.z += p11.x; a1.w += p11.y;
        }
        if (e < end) {
            int s0 = g_col_idx[e];
            uint2 v0 = x2[s0 * 32 + lane];
            float2 p00 = __half22float2(*(__half2*)&v0.x);
            float2 p01 = __half22float2(*(__half2*)&v0.y);
            a0.x += p00.x; a0.y += p00.y; a0.z += p01.x; a0.w += p01.y;
        }
        float sc = g_in_norm[w] * (1.0f / N_NODES);
        atomicAdd(&sacc[lane * 4 + 0], (a0.x + a1.x) * sc);
        atomicAdd(&sacc[lane * 4 + 1], (a0.y + a1.y) * sc);
        atomicAdd(&sacc[lane * 4 + 2], (a0.z + a1.z) * sc);
        atomicAdd(&sacc[lane * 4 + 3], (a0.w + a1.w) * sc);
    }
    __syncthreads();
    if (t < F) atomicAdd(&g_vec[t], sacc[t]);
}

// final 128x128 matvec: out = g_vec @ W3 + b3 (fp32)
__global__ void k_final(const float* __restrict__ W3, const float* __restrict__ b3,
                        float* __restrict__ out) {
    __shared__ float sv[F];
    int j = threadIdx.x;
    sv[j] = g_vec[j];
    __syncthreads();
    float acc = b3[j];
#pragma unroll 8
    for (int k = 0; k < F; k++) acc += sv[k] * W3[k * F + j];
    out[j] = acc;
}

extern "C" void kernel_launch(void* const* d_in, const int* in_sizes, int n_in,
                              void* d_out, int out_size) {
    const float* feat = (const float*)d_in[0];
    const float* W1   = (const float*)d_in[1];
    const float* b1   = (const float*)d_in[2];
    const float* W2   = (const float*)d_in[3];
    const float* b2   = (const float*)d_in[4];
    const float* W3   = (const float*)d_in[5];
    const float* b3   = (const float*)d_in[6];
    const int*   src  = (const int*)d_in[7];
    const int*   dst  = (const int*)d_in[8];
    float* out = (float*)d_out;

    cudaFuncSetAttribute(k_fused, cudaFuncAttributeMaxDynamicSharedMemorySize, SMEM_FUSED);

    void *p0, *p1, *p2;
    cudaGetSymbolAddress(&p0, g_x0);
    cudaGetSymbolAddress(&p1, g_x1);
    cudaGetSymbolAddress(&p2, g_x2);
    __half* x0 = (__half*)p0;
    __half* x1 = (__half*)p1;
    __half* x2 = (__half*)p2;

    int nb_nodes = (N_NODES + 255) / 256;
    int nb_edges = (N_EDGES + 255) / 256;
    int nb_agg   = (N_NODES * 32 + 255) / 256;
    int nb_fused = (N_NODES + GRM - 1) / GRM;        // 391
    int nb_prep  = (N_NODES * F / 4 + 255) / 256;

    // setup: degrees -> CSR by dst -> norms -> fp16 prescaled features
    k_init<<<nb_nodes, 256>>>();
    k_count<<<nb_edges, 256>>>(src, dst);
    k_csr<<<1, CSR_T>>>();
    k_fill<<<nb_edges, 256>>>(src, dst);
    k_prep<<<nb_prep, 256>>>(feat);

    // layers 1-2: fused gather + HMMA GEMM + bias + relu + out_norm prescale
    k_fused<<<nb_fused, 512, SMEM_FUSED>>>(x0, W1, b1, x1);
    k_fused<<<nb_fused, 512, SMEM_FUSED>>>(x1, W2, b2, x2);
    // layer 3: GEMM folded into mean
    k_agg3<<<nb_agg, 256>>>(x2);
    k_final<<<1, F>>>(W3, b3, out);
}